// round 2
// baseline (speedup 1.0000x reference)
#include <cuda_runtime.h>
#include <math.h>

#define BN_ 256      // batch
#define G_  4000     // genes
#define P_  128      // pathways
#define D_  12000    // expert in dim
#define H_  64       // expert hidden
#define O_  16       // expert out
#define GH_ 128      // gate hidden
#define CH_ 8        // classifier hidden
#define C_  5        // classes
#define K_  3        // top_k
#define EPS_ 1e-5f

// ---- gate GEMM1 config ----
#define KS_  20      // K splits
#define KCH_ 200     // 4000 / 20
#define TM_  64
#define TN_  64
#define KT_  8

// ---- expert config ----
#define SCH_ 8       // samples per chunk
#define TR_  128     // rows (active d) per tile
#define MAXITEMS_ 224

// ---------------- device scratch (no allocs allowed) ----------------
__device__ float g_part[KS_ * BN_ * GH_];     // gate gemm1 split-K partials
__device__ int   g_gidx[P_ * G_];             // active gene indices per pathway
__device__ int   g_gcnt[P_];
__device__ int   g_pl_b[P_ * BN_];            // per-pathway sample lists
__device__ float g_pl_w[P_ * BN_];
__device__ int   g_pl_slot[P_ * BN_];
__device__ int   g_pcnt[P_];
__device__ int   g_item_p[MAXITEMS_ + 32];
__device__ int   g_item_c[MAXITEMS_ + 32];
__device__ int   g_nitems;
__device__ float g_contrib[BN_ * K_ * O_];    // per-(sample,slot) expert contribution

__device__ __forceinline__ float neg_inf() { return __int_as_float(0xff800000); }

// ---------------- kernel 1: init ----------------
__global__ void k_init(float* out, int total_out) {
    int i = blockIdx.x * blockDim.x + threadIdx.x;
    if (i < total_out) out[i] = 0.0f;
    if (i < P_) g_pcnt[i] = 0;
    if (i == 0) g_nitems = 0;
}

// ---------------- kernel 2: per-pathway ordered gene compaction ----------------
__global__ void k_compact(const float* __restrict__ mask) {
    int p = blockIdx.x;
    __shared__ int wsum[8];
    __shared__ int sbase;
    int t = threadIdx.x;           // 256
    int lane = t & 31, w = t >> 5;
    if (t == 0) sbase = 0;
    __syncthreads();
    for (int g0 = 0; g0 < G_; g0 += 256) {
        int g = g0 + t;
        int pred = (g < G_) && (mask[g * P_ + p] > 0.5f);
        unsigned bal = __ballot_sync(0xffffffffu, pred);
        if (lane == 0) wsum[w] = __popc(bal);
        __syncthreads();
        int wpre = 0;
        #pragma unroll
        for (int i = 0; i < 8; i++) if (i < w) wpre += wsum[i];
        int total = 0;
        #pragma unroll
        for (int i = 0; i < 8; i++) total += wsum[i];
        if (pred) {
            int off = sbase + wpre + __popc(bal & ((1u << lane) - 1u));
            g_gidx[p * G_ + off] = g;
        }
        __syncthreads();
        if (t == 0) sbase += total;
        __syncthreads();
    }
    if (t == 0) g_gcnt[p] = sbase;
}

// ---------------- kernel 3: gate GEMM1 split-K  C1_part = x_rna @ gate_w1 ----------------
__global__ void k_gemm1(const float* __restrict__ A, const float* __restrict__ Bw) {
    __shared__ __align__(16) float As[KT_][TM_];   // transposed A tile
    __shared__ __align__(16) float Bs[KT_][TN_];
    int m0 = blockIdx.x * TM_;
    int n0 = blockIdx.y * TN_;
    int ks = blockIdx.z;
    int k0 = ks * KCH_;
    int t = threadIdx.x;                 // 256
    int tx = t & 15, ty = t >> 4;        // 16 x 16
    float acc[4][4];
    #pragma unroll
    for (int i = 0; i < 4; i++)
        #pragma unroll
        for (int jj = 0; jj < 4; jj++) acc[i][jj] = 0.0f;

    for (int kk = 0; kk < KCH_; kk += KT_) {
        #pragma unroll
        for (int i = 0; i < 2; i++) {
            int e = t + i * 256;
            int r = e >> 3, c = e & 7;
            As[c][r] = A[(m0 + r) * G_ + k0 + kk + c];
        }
        #pragma unroll
        for (int i = 0; i < 2; i++) {
            int e = t + i * 256;
            int kr = e >> 6, c = e & 63;
            Bs[kr][c] = Bw[(k0 + kk + kr) * GH_ + n0 + c];
        }
        __syncthreads();
        #pragma unroll
        for (int k = 0; k < KT_; k++) {
            float4 a = *(const float4*)&As[k][ty * 4];
            float4 b = *(const float4*)&Bs[k][tx * 4];
            acc[0][0] += a.x * b.x; acc[0][1] += a.x * b.y; acc[0][2] += a.x * b.z; acc[0][3] += a.x * b.w;
            acc[1][0] += a.y * b.x; acc[1][1] += a.y * b.y; acc[1][2] += a.y * b.z; acc[1][3] += a.y * b.w;
            acc[2][0] += a.z * b.x; acc[2][1] += a.z * b.y; acc[2][2] += a.z * b.z; acc[2][3] += a.z * b.w;
            acc[3][0] += a.w * b.x; acc[3][1] += a.w * b.y; acc[3][2] += a.w * b.z; acc[3][3] += a.w * b.w;
        }
        __syncthreads();
    }
    #pragma unroll
    for (int i = 0; i < 4; i++) {
        float4 v = make_float4(acc[i][0], acc[i][1], acc[i][2], acc[i][3]);
        *(float4*)&g_part[(ks * BN_ + m0 + ty * 4 + i) * GH_ + n0 + tx * 4] = v;
    }
}

// ---------------- kernel 4: reduce+relu, gate GEMM2, top-3, lists ----------------
__global__ void k_gate(const float* __restrict__ gb1, const float* __restrict__ W2g,
                       const float* __restrict__ gb2, float* __restrict__ out_gw) {
    int b = blockIdx.x;
    int t = threadIdx.x;                 // 128
    __shared__ float c1s[GH_];
    __shared__ float slog[P_];
    __shared__ float sval[P_];
    __shared__ int   sidx[P_];
    __shared__ float topv[K_];
    __shared__ int   topi[K_];

    float v = gb1[t];
    #pragma unroll
    for (int ks = 0; ks < KS_; ks++) v += g_part[(ks * BN_ + b) * GH_ + t];
    c1s[t] = fmaxf(v, 0.0f);
    __syncthreads();

    float acc = gb2[t];
    #pragma unroll 8
    for (int h = 0; h < GH_; h++) acc += c1s[h] * W2g[h * P_ + t];
    slog[t] = acc;
    __syncthreads();

    for (int k = 0; k < K_; k++) {
        sval[t] = slog[t]; sidx[t] = t;
        __syncthreads();
        for (int s = 64; s > 0; s >>= 1) {
            if (t < s) {
                float v2 = sval[t + s]; int i2 = sidx[t + s];
                if (v2 > sval[t] || (v2 == sval[t] && i2 < sidx[t])) { sval[t] = v2; sidx[t] = i2; }
            }
            __syncthreads();
        }
        if (t == 0) { topv[k] = sval[0]; topi[k] = sidx[0]; slog[sidx[0]] = neg_inf(); }
        __syncthreads();
    }

    if (t < K_) {
        float w = 1.0f / (1.0f + expf(-topv[t]));
        int p = topi[t];
        out_gw[b * P_ + p] = w;
        int pos = atomicAdd(&g_pcnt[p], 1);
        g_pl_b[p * BN_ + pos]    = b;
        g_pl_w[p * BN_ + pos]    = w;
        g_pl_slot[p * BN_ + pos] = t;
    }
}

// ---------------- kernel 5: planner ----------------
__global__ void k_plan() {
    if (threadIdx.x == 0) {
        int m = 0;
        for (int p = 0; p < P_; p++) {
            int n = g_pcnt[p];
            for (int c = 0; c * SCH_ < n && m < MAXITEMS_; c++) {
                g_item_p[m] = p; g_item_c[m] = c * SCH_; m++;
            }
        }
        g_nitems = m;
    }
}

// ---------------- kernel 6: experts (masked-sparse) ----------------
__global__ void __launch_bounds__(256, 2) k_expert(
    const float* __restrict__ x_rna, const float* __restrict__ x_cnv, const float* __restrict__ x_met,
    const float* __restrict__ W1,   const float* __restrict__ eb1,
    const float* __restrict__ gamma,const float* __restrict__ beta,
    const float* __restrict__ mean, const float* __restrict__ var,
    const float* __restrict__ W2,   const float* __restrict__ eb2)
{
    int item = blockIdx.x;
    if (item >= g_nitems) return;
    int p    = g_item_p[item];
    int base = g_item_c[item];
    int cnt  = g_pcnt[p];
    int ns   = min(SCH_, max(0, cnt - base));
    if (ns == 0) return;
    int ng   = g_gcnt[p];
    int R    = ng * 3;

    int t  = threadIdx.x;          // 256
    int j  = t & 63;               // H lane
    int rg = t >> 6;               // row group (4)

    __shared__ int   sb[SCH_];
    __shared__ float swt[SCH_];
    __shared__ int   sslot[SCH_];
    __shared__ __align__(16) float sX[TR_][SCH_];
    __shared__ int   sd[TR_];
    __shared__ float red[4][H_][SCH_ + 1];
    __shared__ float hsh[SCH_][H_];

    if (t < SCH_) {
        if (t < ns) {
            sb[t]    = g_pl_b[p * BN_ + base + t];
            swt[t]   = g_pl_w[p * BN_ + base + t];
            sslot[t] = g_pl_slot[p * BN_ + base + t];
        } else sb[t] = 0;
    }
    __syncthreads();

    float acc[SCH_];
    #pragma unroll
    for (int s = 0; s < SCH_; s++) acc[s] = 0.0f;

    const int* gl = &g_gidx[p * G_];
    int pbase = p * (D_ * H_);

    for (int i0 = 0; i0 < R; i0 += TR_) {
        int nrow = min(TR_, R - i0);
        // phase A: row metadata (d = o*G + g)
        if (t < TR_ && t < nrow) {
            int i = i0 + t;
            int o = i / ng;
            int g = gl[i - o * ng];
            sd[t] = o * G_ + g;
        }
        __syncthreads();
        // phase B: stage x[s][row] (transposed for float4 broadcast)
        for (int e = t; e < TR_ * SCH_; e += 256) {
            int r = e >> 3, s = e & 7;
            float xv = 0.0f;
            if (r < nrow && s < ns) {
                int d = sd[r];
                int o = d / G_;
                int g = d - o * G_;
                const float* xp = (o == 0) ? x_rna : ((o == 1) ? x_cnv : x_met);
                xv = xp[sb[s] * G_ + g];
            }
            sX[r][s] = xv;
        }
        __syncthreads();
        // compute: rows of this row-group
        int rlo = rg * 32;
        int rhi = min(rlo + 32, nrow);
        #pragma unroll 4
        for (int r = rlo; r < rhi; r++) {
            float w = W1[pbase + sd[r] * H_ + j];
            float4 xa = *(const float4*)&sX[r][0];
            float4 xb = *(const float4*)&sX[r][4];
            acc[0] += w * xa.x; acc[1] += w * xa.y; acc[2] += w * xa.z; acc[3] += w * xa.w;
            acc[4] += w * xb.x; acc[5] += w * xb.y; acc[6] += w * xb.z; acc[7] += w * xb.w;
        }
        __syncthreads();
    }

    // cross row-group reduction
    #pragma unroll
    for (int s = 0; s < SCH_; s++) red[rg][j][s] = acc[s];
    __syncthreads();

    if (t < H_) {
        float b1v = eb1[p * H_ + t];
        float mn  = mean[p * H_ + t];
        float sc  = gamma[p * H_ + t] * rsqrtf(var[p * H_ + t] + EPS_);
        float bt  = beta[p * H_ + t];
        #pragma unroll
        for (int s = 0; s < SCH_; s++) {
            float hv = red[0][t][s] + red[1][t][s] + red[2][t][s] + red[3][t][s] + b1v;
            hv = (hv - mn) * sc + bt;
            hsh[s][t] = fmaxf(hv, 0.0f);
        }
    }
    __syncthreads();

    if (t < SCH_ * O_) {
        int s = t >> 4, o = t & 15;
        if (s < ns) {
            float a = eb2[p * O_ + o];
            #pragma unroll 8
            for (int jj = 0; jj < H_; jj++) a += hsh[s][jj] * W2[(p * H_ + jj) * O_ + o];
            g_contrib[(sb[s] * K_ + sslot[s]) * O_ + o] = swt[s] * a;
        }
    }
}

// ---------------- kernel 7: feat sum + classifier ----------------
__global__ void k_final(const float* __restrict__ cw1, const float* __restrict__ cb1,
                        const float* __restrict__ cw2, const float* __restrict__ cb2,
                        float* __restrict__ out_logits) {
    int b = threadIdx.x;   // 256
    float f[O_];
    #pragma unroll
    for (int o = 0; o < O_; o++)
        f[o] = g_contrib[(b * K_ + 0) * O_ + o]
             + g_contrib[(b * K_ + 1) * O_ + o]
             + g_contrib[(b * K_ + 2) * O_ + o];
    float hc[CH_];
    #pragma unroll
    for (int c = 0; c < CH_; c++) {
        float a = cb1[c];
        #pragma unroll
        for (int o = 0; o < O_; o++) a += f[o] * cw1[o * CH_ + c];
        hc[c] = fmaxf(a, 0.0f);
    }
    #pragma unroll
    for (int c = 0; c < C_; c++) {
        float a = cb2[c];
        #pragma unroll
        for (int h = 0; h < CH_; h++) a += hc[h] * cw2[h * C_ + c];
        out_logits[b * C_ + c] = a;
    }
}

// ---------------- launch ----------------
extern "C" void kernel_launch(void* const* d_in, const int* in_sizes, int n_in,
                              void* d_out, int out_size) {
    const float* x_rna     = (const float*)d_in[0];
    const float* x_cnv     = (const float*)d_in[1];
    const float* x_met     = (const float*)d_in[2];
    const float* gene_mask = (const float*)d_in[3];
    const float* gate_w1   = (const float*)d_in[4];
    const float* gate_b1   = (const float*)d_in[5];
    const float* gate_w2   = (const float*)d_in[6];
    const float* gate_b2   = (const float*)d_in[7];
    const float* W1        = (const float*)d_in[8];
    const float* eb1       = (const float*)d_in[9];
    const float* bn_gamma  = (const float*)d_in[10];
    const float* bn_beta   = (const float*)d_in[11];
    const float* bn_mean   = (const float*)d_in[12];
    const float* bn_var    = (const float*)d_in[13];
    const float* W2        = (const float*)d_in[14];
    const float* eb2       = (const float*)d_in[15];
    const float* cls_w1    = (const float*)d_in[16];
    const float* cls_b1    = (const float*)d_in[17];
    const float* cls_w2    = (const float*)d_in[18];
    const float* cls_b2    = (const float*)d_in[19];

    float* out        = (float*)d_out;
    float* out_logits = out;             // [B, C] first (tuple order)
    float* out_gw     = out + BN_ * C_;  // [B, P]

    int total_out = BN_ * C_ + BN_ * P_;
    if (total_out > out_size) total_out = out_size;
    k_init<<<(total_out + 255) / 256, 256>>>(out, total_out);
    k_compact<<<P_, 256>>>(gene_mask);
    dim3 g1(BN_ / TM_, GH_ / TN_, KS_);
    k_gemm1<<<g1, 256>>>(x_rna, gate_w1);
    k_gate<<<BN_, 128>>>(gate_b1, gate_w2, gate_b2, out_gw);
    k_plan<<<1, 32>>>();
    k_expert<<<MAXITEMS_, 256>>>(x_rna, x_cnv, x_met, W1, eb1,
                                 bn_gamma, bn_beta, bn_mean, bn_var, W2, eb2);
    k_final<<<1, 256>>>(cls_w1, cls_b1, cls_w2, cls_b2, out_logits);
}